// round 15
// baseline (speedup 1.0000x reference)
#include <cuda_runtime.h>
#include <math.h>

// Problem constants
#define CUTN    10
#define DMODES  4
#define BATCH   256
#define NLAYERS 4
#define PW      48
#define NBS     48
#define NSEC    19

#define NTHR    384
#define NWARP   12

// Padded state strides (float2 units), all odd -> conflict-light LDS
#define S0P 1111
#define S1P 111
#define S2P 11
#define S3P 1
#define SSZ (9*S0P + 9*S1P + 9*S2P + 9*S3P + 1)   // 11107 float2

typedef unsigned long long u64;

// ---------------------------------------------------------------------------
__device__ __forceinline__ float2 cmul(float2 a, float2 b) {
    return make_float2(a.x*b.x - a.y*b.y, a.x*b.y + a.y*b.x);
}
__device__ __forceinline__ float2 cfma(float2 a, float2 b, float2 acc) {
    acc.x += a.x*b.x - a.y*b.y;
    acc.y += a.x*b.y + a.y*b.x;
    return acc;
}
__device__ __forceinline__ float2 expi(float a) {
    float s, c; sincosf(a, &s, &c);
    return make_float2(c, s);
}

#define FMA2(acc, a, b) \
    asm("fma.rn.f32x2 %0, %1, %2, %0;" : "+l"(acc) : "l"(a), "l"(b))

__device__ __forceinline__ u64 ldphase(const u64* Su, int a, u64 tb, u64 tbs) {
    float2 v = ((const float2*)Su)[a];
    float nvy = -v.y;
    u64 xx, yy, p = 0ULL;
    asm("mov.b64 %0, {%1, %1};" : "=l"(xx) : "f"(v.x));
    asm("mov.b64 %0, {%1, %2};" : "=l"(yy) : "f"(nvy), "f"(v.y));
    FMA2(p, tb, xx); FMA2(p, tbs, yy);
    return p;
}

// ---------------------------------------------------------------------------
// Device scratch.  All gate matrices REAL, duplicated (R,R) for FMA2.
// ---------------------------------------------------------------------------
__device__ float2 g_bs[NBS][100][10];
__device__ float2 g_sq[16][100];
__device__ float2 g_dp[16][100];
__device__ float2 g_S0[100];
__device__ float2 g_Dm[BATCH*DMODES][100];

// Pair strides: p over (0,1),(0,2),(0,3),(1,2),(1,3),(2,3)
__constant__ int cSI[6] = {S0P,S0P,S0P,S1P,S1P,S2P};
__constant__ int cSJ[6] = {S1P,S2P,S3P,S2P,S3P,S3P};
__constant__ int cSA[6] = {S2P,S1P,S1P,S0P,S0P,S0P};
__constant__ int cSB[6] = {S3P,S3P,S2P,S3P,S2P,S1P};
__constant__ int cPI[6] = {0,0,0,1,1,2};
__constant__ int cPJ[6] = {1,2,3,2,3,3};
__constant__ int cMS[4] = {S0P,S1P,S2P,S3P};
__constant__ int cR0[4] = {S1P,S0P,S0P,S0P};
__constant__ int cR1[4] = {S2P,S2P,S1P,S1P};
__constant__ int cR2[4] = {S3P,S3P,S3P,S2P};

// ---------------------------------------------------------------------------
// Kernel 1: build gates (expm). Real generators; phases at runtime.
// ---------------------------------------------------------------------------
#define NJOBS (1 + 1024 + 16 + 16 + NBS*NSEC)

__global__ void build_gates(const float* __restrict__ inputs,
                            const float* __restrict__ w)
{
    __shared__ float2 A[100], E[100], P[100];
    const int job = blockIdx.x;
    const int tid = threadIdx.x;

    int d = CUTN;
    int lo = 0, N = 0, g = 0;
    const bool isBS = (job >= 1057);
    if (isBS) {
        int idx = job - 1057;
        g = idx / NSEC;  N = idx % NSEC;
        lo = max(0, N - (CUTN-1));
        int hi = min(CUTN-1, N);
        d = hi - lo + 1;
    }

    if (tid < d*d) {
        int i = tid / d, j = tid % d;
        float2 v = make_float2(0.f, 0.f);
        if (job == 0) {
            if (i == j-2)      v = make_float2(0.f, -0.25f * sqrtf((float)(j*(j-1))));
            else if (i == j+2) v = make_float2(0.f, -0.25f * sqrtf((float)((j+1)*(j+2))));
        } else if (job <= 1024) {
            float xv = inputs[job-1];
            if (i == j+1)      v = make_float2( xv * sqrtf((float)(j+1)), 0.f);
            else if (i == j-1) v = make_float2(-xv * sqrtf((float)j),     0.f);
        } else if (job <= 1040) {
            int q = job - 1025; int l = q/4, m = q%4;
            float r = w[l*PW + 16 + m];
            if (i == j-2)      v = make_float2( 0.5f*r*sqrtf((float)(j*(j-1))),     0.f);
            else if (i == j+2) v = make_float2(-0.5f*r*sqrtf((float)((j+1)*(j+2))), 0.f);
        } else if (job <= 1056) {
            int q = job - 1041; int l = q/4, m = q%4;
            float rd = w[l*PW + 36 + m];
            if (i == j+1)      v = make_float2( rd * sqrtf((float)(j+1)), 0.f);
            else if (i == j-1) v = make_float2(-rd * sqrtf((float)j),     0.f);
        } else {
            int l = g / 12; int h = (g % 12) / 6; int p = g % 6;
            float th = w[l*PW + (h ? 20 : 0) + p];
            int yi = lo + j; int yj = N - yi;
            if (i == j+1)      v = make_float2( th * sqrtf((float)((yi+1)*yj)), 0.f);
            else if (i == j-1) v = make_float2(-th * sqrtf((float)(yi*(yj+1))), 0.f);
        }
        A[tid] = v;
    }
    __syncthreads();

    const float SC = 1.0f/32.0f;
    if (tid < d*d) {
        int i = tid/d;
        float2 m0 = make_float2(A[tid].x*SC, A[tid].y*SC);
        P[tid] = m0;
        E[tid] = make_float2(((tid % d) == i ? 1.f : 0.f) + m0.x, m0.y);
    }
    __syncthreads();
    for (int k = 2; k <= 8; ++k) {
        float2 t = make_float2(0.f, 0.f);
        if (tid < d*d) {
            int i = tid/d, j = tid%d;
            for (int u = 0; u < d; ++u)
                t = cfma(P[i*d+u], A[u*d+j], t);
            float f = SC / (float)k;
            t.x *= f; t.y *= f;
        }
        __syncthreads();
        if (tid < d*d) {
            E[tid].x += t.x; E[tid].y += t.y;
            P[tid] = t;
        }
        __syncthreads();
    }
    for (int s = 0; s < 5; ++s) {
        float2 t = make_float2(0.f, 0.f);
        if (tid < d*d) {
            int i = tid/d, j = tid%d;
            for (int u = 0; u < d; ++u)
                t = cfma(E[i*d+u], E[u*d+j], t);
        }
        __syncthreads();
        if (tid < d*d) E[tid] = t;
        __syncthreads();
    }

    if (job == 0) {
        if (tid < 100) g_S0[tid] = E[tid];
    } else if (job <= 1024) {
        if (tid < 100) g_Dm[job-1][tid] = E[tid];
    } else if (job <= 1040) {
        if (tid < 100) { float r = E[tid].x; g_sq[job-1025][tid] = make_float2(r, r); }
    } else if (job <= 1056) {
        if (tid < 100) { float r = E[tid].x; g_dp[job-1041][tid] = make_float2(r, r); }
    } else {
        if (tid < d*10) {
            int x = tid/10, t = tid%10;
            int xi = lo + x, xj = N - xi;
            float r = (t < d) ? E[x*d + t].x : 0.f;
            g_bs[g][xi*10 + xj][t] = make_float2(r, r);
        }
    }
}

// ---------------------------------------------------------------------------
// Gate program: 20 gates per layer: 6 BS | 4 SQ | 6 BS | 4 DP
// ---------------------------------------------------------------------------
__device__ __forceinline__ const u64* gate_src(int gi, int& cnt) {
    int lay = gi / 20, r = gi - lay*20;
    if (r < 6)  { cnt = 1000; return (const u64*)&g_bs[lay*12 + r][0][0]; }
    if (r < 10) { cnt = 100;  return (const u64*)&g_sq[lay*4 + (r-6)][0]; }
    if (r < 16) { cnt = 1000; return (const u64*)&g_bs[lay*12 + 6 + (r-10)][0][0]; }
    cnt = 100;  return (const u64*)&g_dp[lay*4 + (r-16)][0];
}

// 384 threads: strides tid, tid+384; third element predicated (1000-768=232).
__device__ __forceinline__ void pre_load(const u64* src, int cnt, int tid, u64* r) {
    r[0] = r[1] = r[2] = 0ULL;
    if (cnt == 1000) {
        r[0] = src[tid]; r[1] = src[tid+384];
        if (tid < 232) r[2] = src[tid+768];
    } else if (tid < 100) {
        r[0] = src[tid];
    }
}
__device__ __forceinline__ void pre_store(u64* dst, int cnt, int tid, const u64* r) {
    if (cnt == 1000) {
        dst[tid] = r[0]; dst[tid+384] = r[1];
        if (tid < 232) dst[tid+768] = r[2];
    } else if (tid < 100) {
        dst[tid] = r[0];
    }
}

// ---------------------------------------------------------------------------
// Circuit kernel: 1-fiber items (low regs -> 12 warps/CTA), real gates +
// pending phases, double-buffered U prefetch, merged phase diagonals.
// ---------------------------------------------------------------------------
template<int D>
__device__ __forceinline__ void bs_item1(u64* Su, const u64* __restrict__ Ub,
        const u64* __restrict__ tab, const u64* __restrict__ tabs,
        int caddr, int ds, int ur0)
{
    u64 inp[D];
#pragma unroll
    for (int t = 0; t < D; ++t)
        inp[t] = ldphase(Su, caddr + t*ds, tab[t], tabs[t]);
#pragma unroll
    for (int x = 0; x < D; ++x) {
        const u64* Ur = Ub + ur0 + x*90;
        u64 a = 0ULL, b = 0ULL;
#pragma unroll
        for (int t = 0; t + 1 < D; t += 2) {
            FMA2(a, Ur[t],   inp[t]);
            FMA2(b, Ur[t+1], inp[t+1]);
        }
        if (D & 1) FMA2(a, Ur[D-1], inp[D-1]);
        asm("add.rn.f32x2 %0, %0, %1;" : "+l"(a) : "l"(b));
        Su[caddr + x*ds] = a;
    }
}

__device__ __forceinline__ void apply_bs(u64* Su, const u64* Ub, u64* Upre,
        const u64* preSrc, int preCnt,
        u64* tab, u64* tabs, float2* pend,
        const int* istart, int p, float phi, int tid)
{
    u64 pr[3];
    pre_load(preSrc, preCnt, tid, pr);

    const int mi = cPI[p], mj = cPJ[p];
    // epoch 1: build phase table (reads pend)
    if (tid < 190) {
        int N = tid / 10, t = tid % 10;
        int lo = (N > 9) ? N - 9 : 0;
        int yi = lo + t, yj = N - yi;
        float2 val = make_float2(0.f, 0.f);
        if (yi <= 9 && yj >= 0) {
            float2 ai = cmul(pend[mi*10 + yi], expi(-phi * (float)yi));
            val = cmul(ai, pend[mj*10 + yj]);
        }
        ((float2*)tab)[tid]  = val;
        ((float2*)tabs)[tid] = make_float2(val.y, val.x);
    }
    __syncthreads();

    // epoch 2: pend reset + compute + prefetch store
    if (tid >= 192 && tid < 212) {
        int t = tid - 192;
        if (t < 10) pend[mi*10 + t] = expi(phi * (float)t);
        else        pend[mj*10 + (t-10)] = make_float2(1.f, 0.f);
    }

    const int sj = cSJ[p], sa = cSA[p], sb = cSB[p];
    const int ds = cSI[p] - sj;
    const int wid = tid >> 5, lane = tid & 31;
    const int i1 = istart[wid+1];

    for (int it = istart[wid] + lane; it < i1; it += 32) {
        int N  = it / 100;
        int q  = it - N*100;
        int fa = q / 10, fb = q - fa*10;
        int base = fa*sa + fb*sb;
        int lo = (N > 9) ? N - 9 : 0;
        int hi = (N < 9) ? N : 9;
        int d  = hi - lo + 1;
        int caddr = base + N*sj + lo*ds;
        int ur0   = (9*lo + N)*10;
        const u64* tN  = tab  + N*10;
        const u64* tNs = tabs + N*10;
        switch (d) {
            case  1: bs_item1< 1>(Su, Ub, tN, tNs, caddr, ds, ur0); break;
            case  2: bs_item1< 2>(Su, Ub, tN, tNs, caddr, ds, ur0); break;
            case  3: bs_item1< 3>(Su, Ub, tN, tNs, caddr, ds, ur0); break;
            case  4: bs_item1< 4>(Su, Ub, tN, tNs, caddr, ds, ur0); break;
            case  5: bs_item1< 5>(Su, Ub, tN, tNs, caddr, ds, ur0); break;
            case  6: bs_item1< 6>(Su, Ub, tN, tNs, caddr, ds, ur0); break;
            case  7: bs_item1< 7>(Su, Ub, tN, tNs, caddr, ds, ur0); break;
            case  8: bs_item1< 8>(Su, Ub, tN, tNs, caddr, ds, ur0); break;
            case  9: bs_item1< 9>(Su, Ub, tN, tNs, caddr, ds, ur0); break;
            default: bs_item1<10>(Su, Ub, tN, tNs, caddr, ds, ur0); break;
        }
    }

    pre_store(Upre, preCnt, tid, pr);
    __syncthreads();
}

// Single-mode gate with merged diagonals:
//   tab  = pend * expi((vpm - phi)*n)
//   pend = expi(phi*n + kerr*n^2)
__device__ __forceinline__ void apply_single(u64* Su, const u64* Ub, u64* Upre,
        const u64* preSrc, int preCnt,
        u64* tab, u64* tabs, float2* pend,
        int m, float phi, float vpm, float kerr, int tid)
{
    u64 pr[3];
    pre_load(preSrc, preCnt, tid, pr);

    if (tid < 10) {
        float2 val = cmul(pend[m*10 + tid], expi((vpm - phi) * (float)tid));
        ((float2*)tab)[tid]  = val;
        ((float2*)tabs)[tid] = make_float2(val.y, val.x);
    }
    __syncthreads();

    if (tid < 10) {
        float t = (float)tid;
        pend[m*10 + tid] = expi(phi * t + kerr * t * t);
    }

    const int sm = cMS[m], r0 = cR0[m], r1 = cR1[m], r2 = cR2[m];

    for (int it = tid; it < 1000; it += NTHR) {
        int f0 = it / 100;
        int rm = it - f0*100;
        int f1 = rm / 10, f2 = rm - f1*10;
        int base = f0*r0 + f1*r1 + f2*r2;
        u64 inp[10];
#pragma unroll
        for (int y = 0; y < 10; ++y)
            inp[y] = ldphase(Su, base + y*sm, tab[y], tabs[y]);
#pragma unroll
        for (int x = 0; x < 10; ++x) {
            const u64* Ur = Ub + x*10;
            u64 a = 0ULL, b = 0ULL;
#pragma unroll
            for (int y = 0; y < 10; y += 2) {
                FMA2(a, Ur[y],   inp[y]);
                FMA2(b, Ur[y+1], inp[y+1]);
            }
            asm("add.rn.f32x2 %0, %0, %1;" : "+l"(a) : "l"(b));
            Su[base + x*sm] = a;
        }
    }

    pre_store(Upre, preCnt, tid, pr);
    __syncthreads();
}

__global__ void __launch_bounds__(NTHR, 2)
circuit(const float* __restrict__ w, float* __restrict__ out)
{
    extern __shared__ float2 sh[];
    float2* S    = sh;                    // 11107
    float2* Ub0F = sh + SSZ;              // 1000
    float2* Ub1F = sh + SSZ + 1000;       // 1000
    float2* tabF = sh + SSZ + 2000;       // 190
    float2* tbsF = sh + SSZ + 2190;       // 190
    float2* pend = sh + SSZ + 2380;       // 40
    float2* PV   = sh + SSZ + 2420;       // 40
    __shared__ int istart[NWARP + 1];
    __shared__ float red[NWARP*4];

    const int b = blockIdx.x, tid = threadIdx.x;
    u64* Su  = (u64*)S;
    u64* Ub0 = (u64*)Ub0F;
    u64* Ub1 = (u64*)Ub1F;
    u64* tab = (u64*)tabF;
    u64* tbs = (u64*)tbsF;

    // balanced warp partition of the 1900 1-fiber BS items (static weights)
    if (tid < NWARP + 1) {
        int wn[19]; long long W = 0;
        for (int N = 0; N < 19; ++N) {
            int d = min(min(N + 1, 19 - N), 10);
            wn[N] = 100 * (d*d + 6*d + 8);
            W += wn[N];
        }
        long long tw = (long long)tid * W / NWARP;
        int N = 0; long long cum = 0;
        while (N < 18 && cum + wn[N] <= tw) { cum += wn[N]; N++; }
        int d = min(min(N + 1, 19 - N), 10);
        int k = (int)((tw - cum) / (d*d + 6*d + 8));
        if (k > 100) k = 100;
        istart[tid] = N*100 + k;
    }

    // stage gate 0 into Ub0 (overlaps psi computation)
    {
        int c; const u64* s = gate_src(0, c);
        for (int q = tid; q < c; q += NTHR) Ub0[q] = s[q];
    }

    // per-mode initial vectors: psi[m] = Dm[b*4+m] @ S0[:,0]
    if (tid >= 64 && tid < 104) {
        int t = tid - 64;
        int mode = t / 10, row = t % 10;
        const float2* Dm = &g_Dm[b*4 + mode][row*10];
        float2 acc = make_float2(0.f, 0.f);
#pragma unroll
        for (int y = 0; y < 10; ++y) acc = cfma(Dm[y], g_S0[y*10], acc);
        PV[t]   = acc;
        pend[t] = make_float2(1.f, 0.f);
    }
    __syncthreads();

    // initial product state
    for (int o = tid; o < 10000; o += NTHR) {
        int i = o/1000, j = (o/100)%10, kk = (o/10)%10, l = o%10;
        S[o + i*111 + j*11 + kk] = cmul(cmul(PV[i], PV[10+j]), cmul(PV[20+kk], PV[30+l]));
    }
    __syncthreads();

    int gi = 0, cur = 0;
    for (int lay = 0; lay < NLAYERS; ++lay) {
        const float* wl = w + lay*PW;
        for (int p = 0; p < 6; ++p) {
            int c; const u64* ns = gate_src((gi + 1) % 80, c);
            apply_bs(Su, cur ? Ub1 : Ub0, cur ? Ub0 : Ub1, ns, c,
                     tab, tbs, pend, istart, p, wl[6+p], tid);
            cur ^= 1; gi++;
        }
        for (int m = 0; m < 4; ++m) {
            int c; const u64* ns = gate_src((gi + 1) % 80, c);
            apply_single(Su, cur ? Ub1 : Ub0, cur ? Ub0 : Ub1, ns, c,
                         tab, tbs, pend, m, 0.f, wl[12+m], 0.f, tid);
            cur ^= 1; gi++;
        }
        for (int p = 0; p < 6; ++p) {
            int c; const u64* ns = gate_src((gi + 1) % 80, c);
            apply_bs(Su, cur ? Ub1 : Ub0, cur ? Ub0 : Ub1, ns, c,
                     tab, tbs, pend, istart, p, wl[26+p], tid);
            cur ^= 1; gi++;
        }
        for (int m = 0; m < 4; ++m) {
            int c; const u64* ns = gate_src((gi + 1) % 80, c);
            apply_single(Su, cur ? Ub1 : Ub0, cur ? Ub0 : Ub1, ns, c,
                         tab, tbs, pend, m, wl[40+m], wl[32+m], wl[44+m], tid);
            cur ^= 1; gi++;
        }
    }
    // final pending phases are diagonal -> invisible in |psi|^2

    // <n_m> readout
    float a0 = 0.f, a1 = 0.f, a2 = 0.f, a3 = 0.f;
    for (int o = tid; o < 10000; o += NTHR) {
        int i = o/1000, j = (o/100)%10, kk = (o/10)%10, l = o%10;
        float2 s = S[o + i*111 + j*11 + kk];
        float pr = s.x*s.x + s.y*s.y;
        a0 += pr * (float)i;
        a1 += pr * (float)j;
        a2 += pr * (float)kk;
        a3 += pr * (float)l;
    }
#pragma unroll
    for (int off = 16; off > 0; off >>= 1) {
        a0 += __shfl_down_sync(0xffffffffu, a0, off);
        a1 += __shfl_down_sync(0xffffffffu, a1, off);
        a2 += __shfl_down_sync(0xffffffffu, a2, off);
        a3 += __shfl_down_sync(0xffffffffu, a3, off);
    }
    int wid = tid / 32, lane = tid % 32;
    if (lane == 0) {
        red[wid*4 + 0] = a0; red[wid*4 + 1] = a1;
        red[wid*4 + 2] = a2; red[wid*4 + 3] = a3;
    }
    __syncthreads();
    if (tid < 4) {
        float s = 0.f;
        for (int ww = 0; ww < NWARP; ++ww) s += red[ww*4 + tid];
        out[b*4 + tid] = s;
    }
}

// ---------------------------------------------------------------------------
#define CIRCUIT_SMEM ((SSZ + 2460) * (int)sizeof(float2))   // 108,536 B

extern "C" void kernel_launch(void* const* d_in, const int* in_sizes, int n_in,
                              void* d_out, int out_size)
{
    const float* inputs  = (const float*)d_in[0];
    const float* weights = (const float*)d_in[1];
    float* out = (float*)d_out;

    cudaFuncSetAttribute(circuit, cudaFuncAttributeMaxDynamicSharedMemorySize, CIRCUIT_SMEM);

    build_gates<<<NJOBS, 128>>>(inputs, weights);
    circuit<<<BATCH, NTHR, CIRCUIT_SMEM>>>(weights, out);
}

// round 16
// speedup vs baseline: 1.0973x; 1.0973x over previous
#include <cuda_runtime.h>
#include <math.h>

// Problem constants
#define CUTN    10
#define DMODES  4
#define BATCH   256
#define NLAYERS 4
#define PW      48
#define NBS     48
#define NSEC    19

#define NTHR    384
#define NWARP   12

// Padded state strides (float2 units), all odd -> conflict-light LDS
#define S0P 1111
#define S1P 111
#define S2P 11
#define S3P 1
#define SSZ (9*S0P + 9*S1P + 9*S2P + 9*S3P + 1)   // 11107 float2

typedef unsigned long long u64;
#define SGN64 0x8000000080000000ULL

// ---------------------------------------------------------------------------
__device__ __forceinline__ float2 cmul(float2 a, float2 b) {
    return make_float2(a.x*b.x - a.y*b.y, a.x*b.y + a.y*b.x);
}
__device__ __forceinline__ float2 cfma(float2 a, float2 b, float2 acc) {
    acc.x += a.x*b.x - a.y*b.y;
    acc.y += a.x*b.y + a.y*b.x;
    return acc;
}
__device__ __forceinline__ float2 expi(float a) {
    float s, c; sincosf(a, &s, &c);
    return make_float2(c, s);
}

#define FMA2(acc, a, b) \
    asm("fma.rn.f32x2 %0, %1, %2, %0;" : "+l"(acc) : "l"(a), "l"(b))
#define ADD2(out, a, b) \
    asm("add.rn.f32x2 %0, %1, %2;" : "=l"(out) : "l"(a), "l"(b))

__device__ __forceinline__ u64 ldphase(const u64* Su, int a, u64 tb, u64 tbs) {
    float2 v = ((const float2*)Su)[a];
    float nvy = -v.y;
    u64 xx, yy, p = 0ULL;
    asm("mov.b64 %0, {%1, %1};" : "=l"(xx) : "f"(v.x));
    asm("mov.b64 %0, {%1, %2};" : "=l"(yy) : "f"(nvy), "f"(v.y));
    FMA2(p, tb, xx); FMA2(p, tbs, yy);
    return p;
}

// ---------------------------------------------------------------------------
// Device scratch.  All gate matrices REAL, duplicated (R,R) for FMA2.
// ---------------------------------------------------------------------------
__device__ float2 g_bs[NBS][100][10];
__device__ float2 g_sq[16][100];
__device__ float2 g_dp[16][100];
__device__ float2 g_S0[100];
__device__ float2 g_Dm[BATCH*DMODES][100];

// Pair strides: p over (0,1),(0,2),(0,3),(1,2),(1,3),(2,3)
__constant__ int cSI[6] = {S0P,S0P,S0P,S1P,S1P,S2P};
__constant__ int cSJ[6] = {S1P,S2P,S3P,S2P,S3P,S3P};
__constant__ int cSA[6] = {S2P,S1P,S1P,S0P,S0P,S0P};
__constant__ int cSB[6] = {S3P,S3P,S2P,S3P,S2P,S1P};
__constant__ int cPI[6] = {0,0,0,1,1,2};
__constant__ int cPJ[6] = {1,2,3,2,3,3};
__constant__ int cMS[4] = {S0P,S1P,S2P,S3P};
__constant__ int cR0[4] = {S1P,S0P,S0P,S0P};
__constant__ int cR1[4] = {S2P,S2P,S1P,S1P};
__constant__ int cR2[4] = {S3P,S3P,S3P,S2P};

// ---------------------------------------------------------------------------
// Kernel 1: build gates (expm). Real generators; phases at runtime.
// ---------------------------------------------------------------------------
#define NJOBS (1 + 1024 + 16 + 16 + NBS*NSEC)

__global__ void build_gates(const float* __restrict__ inputs,
                            const float* __restrict__ w)
{
    __shared__ float2 A[100], E[100], P[100];
    const int job = blockIdx.x;
    const int tid = threadIdx.x;

    int d = CUTN;
    int lo = 0, N = 0, g = 0;
    const bool isBS = (job >= 1057);
    if (isBS) {
        int idx = job - 1057;
        g = idx / NSEC;  N = idx % NSEC;
        lo = max(0, N - (CUTN-1));
        int hi = min(CUTN-1, N);
        d = hi - lo + 1;
    }

    if (tid < d*d) {
        int i = tid / d, j = tid % d;
        float2 v = make_float2(0.f, 0.f);
        if (job == 0) {
            if (i == j-2)      v = make_float2(0.f, -0.25f * sqrtf((float)(j*(j-1))));
            else if (i == j+2) v = make_float2(0.f, -0.25f * sqrtf((float)((j+1)*(j+2))));
        } else if (job <= 1024) {
            float xv = inputs[job-1];
            if (i == j+1)      v = make_float2( xv * sqrtf((float)(j+1)), 0.f);
            else if (i == j-1) v = make_float2(-xv * sqrtf((float)j),     0.f);
        } else if (job <= 1040) {
            int q = job - 1025; int l = q/4, m = q%4;
            float r = w[l*PW + 16 + m];
            if (i == j-2)      v = make_float2( 0.5f*r*sqrtf((float)(j*(j-1))),     0.f);
            else if (i == j+2) v = make_float2(-0.5f*r*sqrtf((float)((j+1)*(j+2))), 0.f);
        } else if (job <= 1056) {
            int q = job - 1041; int l = q/4, m = q%4;
            float rd = w[l*PW + 36 + m];
            if (i == j+1)      v = make_float2( rd * sqrtf((float)(j+1)), 0.f);
            else if (i == j-1) v = make_float2(-rd * sqrtf((float)j),     0.f);
        } else {
            int l = g / 12; int h = (g % 12) / 6; int p = g % 6;
            float th = w[l*PW + (h ? 20 : 0) + p];
            int yi = lo + j; int yj = N - yi;
            if (i == j+1)      v = make_float2( th * sqrtf((float)((yi+1)*yj)), 0.f);
            else if (i == j-1) v = make_float2(-th * sqrtf((float)(yi*(yj+1))), 0.f);
        }
        A[tid] = v;
    }
    __syncthreads();

    const float SC = 1.0f/32.0f;
    if (tid < d*d) {
        int i = tid/d;
        float2 m0 = make_float2(A[tid].x*SC, A[tid].y*SC);
        P[tid] = m0;
        E[tid] = make_float2(((tid % d) == i ? 1.f : 0.f) + m0.x, m0.y);
    }
    __syncthreads();
    for (int k = 2; k <= 8; ++k) {
        float2 t = make_float2(0.f, 0.f);
        if (tid < d*d) {
            int i = tid/d, j = tid%d;
            for (int u = 0; u < d; ++u)
                t = cfma(P[i*d+u], A[u*d+j], t);
            float f = SC / (float)k;
            t.x *= f; t.y *= f;
        }
        __syncthreads();
        if (tid < d*d) {
            E[tid].x += t.x; E[tid].y += t.y;
            P[tid] = t;
        }
        __syncthreads();
    }
    for (int s = 0; s < 5; ++s) {
        float2 t = make_float2(0.f, 0.f);
        if (tid < d*d) {
            int i = tid/d, j = tid%d;
            for (int u = 0; u < d; ++u)
                t = cfma(E[i*d+u], E[u*d+j], t);
        }
        __syncthreads();
        if (tid < d*d) E[tid] = t;
        __syncthreads();
    }

    if (job == 0) {
        if (tid < 100) g_S0[tid] = E[tid];
    } else if (job <= 1024) {
        if (tid < 100) g_Dm[job-1][tid] = E[tid];
    } else if (job <= 1040) {
        if (tid < 100) { float r = E[tid].x; g_sq[job-1025][tid] = make_float2(r, r); }
    } else if (job <= 1056) {
        if (tid < 100) { float r = E[tid].x; g_dp[job-1041][tid] = make_float2(r, r); }
    } else {
        if (tid < d*10) {
            int x = tid/10, t = tid%10;
            int xi = lo + x, xj = N - xi;
            float r = (t < d) ? E[x*d + t].x : 0.f;
            g_bs[g][xi*10 + xj][t] = make_float2(r, r);
        }
    }
}

// ---------------------------------------------------------------------------
// Gate program: 20 gates per layer: 6 BS | 4 SQ | 6 BS | 4 DP
// ---------------------------------------------------------------------------
__device__ __forceinline__ const u64* gate_src(int gi, int& cnt) {
    int lay = gi / 20, r = gi - lay*20;
    if (r < 6)  { cnt = 1000; return (const u64*)&g_bs[lay*12 + r][0][0]; }
    if (r < 10) { cnt = 100;  return (const u64*)&g_sq[lay*4 + (r-6)][0]; }
    if (r < 16) { cnt = 1000; return (const u64*)&g_bs[lay*12 + 6 + (r-10)][0][0]; }
    cnt = 100;  return (const u64*)&g_dp[lay*4 + (r-16)][0];
}

// 384 threads: strides tid, tid+384; third element predicated (1000-768=232).
__device__ __forceinline__ void pre_load(const u64* src, int cnt, int tid, u64* r) {
    r[0] = r[1] = r[2] = 0ULL;
    if (cnt == 1000) {
        r[0] = src[tid]; r[1] = src[tid+384];
        if (tid < 232) r[2] = src[tid+768];
    } else if (tid < 100) {
        r[0] = src[tid];
    }
}
__device__ __forceinline__ void pre_store(u64* dst, int cnt, int tid, const u64* r) {
    if (cnt == 1000) {
        dst[tid] = r[0]; dst[tid+384] = r[1];
        if (tid < 232) dst[tid+768] = r[2];
    } else if (tid < 100) {
        dst[tid] = r[0];
    }
}

// ---------------------------------------------------------------------------
// Circuit kernel.  BS items exploit the persymmetry of the real sector
// matrix E[x][t] = (-1)^{x+t} E[d-1-x][d-1-t]: each U-row load feeds the
// row pair (x, d-1-x), halving U shared-memory loads.
// ---------------------------------------------------------------------------
template<int D>
__device__ __forceinline__ void bs_item1(u64* Su, const u64* __restrict__ Ub,
        const u64* __restrict__ tab, const u64* __restrict__ tabs,
        int caddr, int ds, int ur0)
{
    u64 inp[D];
#pragma unroll
    for (int t = 0; t < D; ++t)
        inp[t] = ldphase(Su, caddr + t*ds, tab[t], tabs[t]);

    // paired rows (x, D-1-x)
#pragma unroll
    for (int x = 0; x < D/2; ++x) {
        const u64* Ur = Ub + ur0 + x*90;
        u64 p0 = 0ULL, p1 = 0ULL, qe = 0ULL, qo = 0ULL;
#pragma unroll
        for (int t = 0; t < D; ++t) {
            u64 u = Ur[t];
            if ((t & 1) == 0) { FMA2(p0, u, inp[t]); FMA2(qe, u, inp[D-1-t]); }
            else              { FMA2(p1, u, inp[t]); FMA2(qo, u, inp[D-1-t]); }
        }
        u64 o1; ADD2(o1, p0, p1);
        u64 o2;
        if ((x & 1) == 0) { u64 n = qo ^ SGN64; ADD2(o2, qe, n); }
        else              { u64 n = qe ^ SGN64; ADD2(o2, qo, n); }
        Su[caddr + x*ds]       = o1;
        Su[caddr + (D-1-x)*ds] = o2;
    }
    if (D & 1) {
        const int x = D/2;
        const u64* Ur = Ub + ur0 + x*90;
        u64 p0 = 0ULL, p1 = 0ULL;
#pragma unroll
        for (int t = 0; t + 1 < D; t += 2) {
            FMA2(p0, Ur[t],   inp[t]);
            FMA2(p1, Ur[t+1], inp[t+1]);
        }
        FMA2(p0, Ur[D-1], inp[D-1]);
        u64 o; ADD2(o, p0, p1);
        Su[caddr + x*ds] = o;
    }
}

__device__ __forceinline__ void apply_bs(u64* Su, const u64* Ub, u64* Upre,
        const u64* preSrc, int preCnt,
        u64* tab, u64* tabs, float2* pend,
        const int* istart, int p, float phi, int tid)
{
    u64 pr[3];
    pre_load(preSrc, preCnt, tid, pr);

    const int mi = cPI[p], mj = cPJ[p];
    // epoch 1: build phase table (reads pend)
    if (tid < 190) {
        int N = tid / 10, t = tid % 10;
        int lo = (N > 9) ? N - 9 : 0;
        int yi = lo + t, yj = N - yi;
        float2 val = make_float2(0.f, 0.f);
        if (yi <= 9 && yj >= 0) {
            float2 ai = cmul(pend[mi*10 + yi], expi(-phi * (float)yi));
            val = cmul(ai, pend[mj*10 + yj]);
        }
        ((float2*)tab)[tid]  = val;
        ((float2*)tabs)[tid] = make_float2(val.y, val.x);
    }
    __syncthreads();

    // epoch 2: pend reset + compute + prefetch store
    if (tid >= 192 && tid < 212) {
        int t = tid - 192;
        if (t < 10) pend[mi*10 + t] = expi(phi * (float)t);
        else        pend[mj*10 + (t-10)] = make_float2(1.f, 0.f);
    }

    const int sj = cSJ[p], sa = cSA[p], sb = cSB[p];
    const int ds = cSI[p] - sj;
    const int wid = tid >> 5, lane = tid & 31;
    const int i1 = istart[wid+1];

    for (int it = istart[wid] + lane; it < i1; it += 32) {
        int N  = it / 100;
        int q  = it - N*100;
        int fa = q / 10, fb = q - fa*10;
        int base = fa*sa + fb*sb;
        int lo = (N > 9) ? N - 9 : 0;
        int hi = (N < 9) ? N : 9;
        int d  = hi - lo + 1;
        int caddr = base + N*sj + lo*ds;
        int ur0   = (9*lo + N)*10;
        const u64* tN  = tab  + N*10;
        const u64* tNs = tabs + N*10;
        switch (d) {
            case  1: bs_item1< 1>(Su, Ub, tN, tNs, caddr, ds, ur0); break;
            case  2: bs_item1< 2>(Su, Ub, tN, tNs, caddr, ds, ur0); break;
            case  3: bs_item1< 3>(Su, Ub, tN, tNs, caddr, ds, ur0); break;
            case  4: bs_item1< 4>(Su, Ub, tN, tNs, caddr, ds, ur0); break;
            case  5: bs_item1< 5>(Su, Ub, tN, tNs, caddr, ds, ur0); break;
            case  6: bs_item1< 6>(Su, Ub, tN, tNs, caddr, ds, ur0); break;
            case  7: bs_item1< 7>(Su, Ub, tN, tNs, caddr, ds, ur0); break;
            case  8: bs_item1< 8>(Su, Ub, tN, tNs, caddr, ds, ur0); break;
            case  9: bs_item1< 9>(Su, Ub, tN, tNs, caddr, ds, ur0); break;
            default: bs_item1<10>(Su, Ub, tN, tNs, caddr, ds, ur0); break;
        }
    }

    pre_store(Upre, preCnt, tid, pr);
    __syncthreads();
}

// Single-mode gate with merged diagonals:
//   tab  = pend * expi((vpm - phi)*n)
//   pend = expi(phi*n + kerr*n^2)
__device__ __forceinline__ void apply_single(u64* Su, const u64* Ub, u64* Upre,
        const u64* preSrc, int preCnt,
        u64* tab, u64* tabs, float2* pend,
        int m, float phi, float vpm, float kerr, int tid)
{
    u64 pr[3];
    pre_load(preSrc, preCnt, tid, pr);

    if (tid < 10) {
        float2 val = cmul(pend[m*10 + tid], expi((vpm - phi) * (float)tid));
        ((float2*)tab)[tid]  = val;
        ((float2*)tabs)[tid] = make_float2(val.y, val.x);
    }
    __syncthreads();

    if (tid < 10) {
        float t = (float)tid;
        pend[m*10 + tid] = expi(phi * t + kerr * t * t);
    }

    const int sm = cMS[m], r0 = cR0[m], r1 = cR1[m], r2 = cR2[m];

    for (int it = tid; it < 1000; it += NTHR) {
        int f0 = it / 100;
        int rm = it - f0*100;
        int f1 = rm / 10, f2 = rm - f1*10;
        int base = f0*r0 + f1*r1 + f2*r2;
        u64 inp[10];
#pragma unroll
        for (int y = 0; y < 10; ++y)
            inp[y] = ldphase(Su, base + y*sm, tab[y], tabs[y]);
#pragma unroll
        for (int x = 0; x < 10; ++x) {
            const u64* Ur = Ub + x*10;
            u64 a = 0ULL, b = 0ULL;
#pragma unroll
            for (int y = 0; y < 10; y += 2) {
                FMA2(a, Ur[y],   inp[y]);
                FMA2(b, Ur[y+1], inp[y+1]);
            }
            asm("add.rn.f32x2 %0, %0, %1;" : "+l"(a) : "l"(b));
            Su[base + x*sm] = a;
        }
    }

    pre_store(Upre, preCnt, tid, pr);
    __syncthreads();
}

__global__ void __launch_bounds__(NTHR, 2)
circuit(const float* __restrict__ w, float* __restrict__ out)
{
    extern __shared__ float2 sh[];
    float2* S    = sh;                    // 11107
    float2* Ub0F = sh + SSZ;              // 1000
    float2* Ub1F = sh + SSZ + 1000;       // 1000
    float2* tabF = sh + SSZ + 2000;       // 190
    float2* tbsF = sh + SSZ + 2190;       // 190
    float2* pend = sh + SSZ + 2380;       // 40
    float2* PV   = sh + SSZ + 2420;       // 40
    __shared__ int istart[NWARP + 1];
    __shared__ float red[NWARP*4];

    const int b = blockIdx.x, tid = threadIdx.x;
    u64* Su  = (u64*)S;
    u64* Ub0 = (u64*)Ub0F;
    u64* Ub1 = (u64*)Ub1F;
    u64* tab = (u64*)tabF;
    u64* tbs = (u64*)tbsF;

    // balanced warp partition of the 1900 1-fiber BS items (static weights)
    if (tid < NWARP + 1) {
        int wn[19]; long long W = 0;
        for (int N = 0; N < 19; ++N) {
            int d = min(min(N + 1, 19 - N), 10);
            wn[N] = 100 * (d*d/2 + 7*d + 8);   // symmetry-adjusted weight
            W += wn[N];
        }
        long long tw = (long long)tid * W / NWARP;
        int N = 0; long long cum = 0;
        while (N < 18 && cum + wn[N] <= tw) { cum += wn[N]; N++; }
        int d = min(min(N + 1, 19 - N), 10);
        int k = (int)((tw - cum) / (d*d/2 + 7*d + 8));
        if (k > 100) k = 100;
        istart[tid] = N*100 + k;
    }

    // stage gate 0 into Ub0 (overlaps psi computation)
    {
        int c; const u64* s = gate_src(0, c);
        for (int q = tid; q < c; q += NTHR) Ub0[q] = s[q];
    }

    // per-mode initial vectors: psi[m] = Dm[b*4+m] @ S0[:,0]
    if (tid >= 64 && tid < 104) {
        int t = tid - 64;
        int mode = t / 10, row = t % 10;
        const float2* Dm = &g_Dm[b*4 + mode][row*10];
        float2 acc = make_float2(0.f, 0.f);
#pragma unroll
        for (int y = 0; y < 10; ++y) acc = cfma(Dm[y], g_S0[y*10], acc);
        PV[t]   = acc;
        pend[t] = make_float2(1.f, 0.f);
    }
    __syncthreads();

    // initial product state
    for (int o = tid; o < 10000; o += NTHR) {
        int i = o/1000, j = (o/100)%10, kk = (o/10)%10, l = o%10;
        S[o + i*111 + j*11 + kk] = cmul(cmul(PV[i], PV[10+j]), cmul(PV[20+kk], PV[30+l]));
    }
    __syncthreads();

    int gi = 0, cur = 0;
    for (int lay = 0; lay < NLAYERS; ++lay) {
        const float* wl = w + lay*PW;
        for (int p = 0; p < 6; ++p) {
            int c; const u64* ns = gate_src((gi + 1) % 80, c);
            apply_bs(Su, cur ? Ub1 : Ub0, cur ? Ub0 : Ub1, ns, c,
                     tab, tbs, pend, istart, p, wl[6+p], tid);
            cur ^= 1; gi++;
        }
        for (int m = 0; m < 4; ++m) {
            int c; const u64* ns = gate_src((gi + 1) % 80, c);
            apply_single(Su, cur ? Ub1 : Ub0, cur ? Ub0 : Ub1, ns, c,
                         tab, tbs, pend, m, 0.f, wl[12+m], 0.f, tid);
            cur ^= 1; gi++;
        }
        for (int p = 0; p < 6; ++p) {
            int c; const u64* ns = gate_src((gi + 1) % 80, c);
            apply_bs(Su, cur ? Ub1 : Ub0, cur ? Ub0 : Ub1, ns, c,
                     tab, tbs, pend, istart, p, wl[26+p], tid);
            cur ^= 1; gi++;
        }
        for (int m = 0; m < 4; ++m) {
            int c; const u64* ns = gate_src((gi + 1) % 80, c);
            apply_single(Su, cur ? Ub1 : Ub0, cur ? Ub0 : Ub1, ns, c,
                         tab, tbs, pend, m, wl[40+m], wl[32+m], wl[44+m], tid);
            cur ^= 1; gi++;
        }
    }
    // final pending phases are diagonal -> invisible in |psi|^2

    // <n_m> readout
    float a0 = 0.f, a1 = 0.f, a2 = 0.f, a3 = 0.f;
    for (int o = tid; o < 10000; o += NTHR) {
        int i = o/1000, j = (o/100)%10, kk = (o/10)%10, l = o%10;
        float2 s = S[o + i*111 + j*11 + kk];
        float pr = s.x*s.x + s.y*s.y;
        a0 += pr * (float)i;
        a1 += pr * (float)j;
        a2 += pr * (float)kk;
        a3 += pr * (float)l;
    }
#pragma unroll
    for (int off = 16; off > 0; off >>= 1) {
        a0 += __shfl_down_sync(0xffffffffu, a0, off);
        a1 += __shfl_down_sync(0xffffffffu, a1, off);
        a2 += __shfl_down_sync(0xffffffffu, a2, off);
        a3 += __shfl_down_sync(0xffffffffu, a3, off);
    }
    int wid = tid / 32, lane = tid % 32;
    if (lane == 0) {
        red[wid*4 + 0] = a0; red[wid*4 + 1] = a1;
        red[wid*4 + 2] = a2; red[wid*4 + 3] = a3;
    }
    __syncthreads();
    if (tid < 4) {
        float s = 0.f;
        for (int ww = 0; ww < NWARP; ++ww) s += red[ww*4 + tid];
        out[b*4 + tid] = s;
    }
}

// ---------------------------------------------------------------------------
#define CIRCUIT_SMEM ((SSZ + 2460) * (int)sizeof(float2))   // 108,536 B

extern "C" void kernel_launch(void* const* d_in, const int* in_sizes, int n_in,
                              void* d_out, int out_size)
{
    const float* inputs  = (const float*)d_in[0];
    const float* weights = (const float*)d_in[1];
    float* out = (float*)d_out;

    cudaFuncSetAttribute(circuit, cudaFuncAttributeMaxDynamicSharedMemorySize, CIRCUIT_SMEM);

    build_gates<<<NJOBS, 128>>>(inputs, weights);
    circuit<<<BATCH, NTHR, CIRCUIT_SMEM>>>(weights, out);
}